// round 1
// baseline (speedup 1.0000x reference)
#include <cuda_runtime.h>
#include <cuda_bf16.h>
#include <cstdint>

// Problem constants
#define BB   8
#define CIN  128
#define COUT 128
#define HH   128
#define WW   128
#define RNK  32
#define BR   4
#define HW   (HH*WW)
#define K3   (3.0f/128.0f)

// Scratch (no allocation allowed)
__device__ float g_vproj[BB*CIN*16];   // (b, i, p*4+q)
__device__ float g_m[BB*COUT*16];      // (b, o, p*4+q)

__device__ __forceinline__ float hatf(float d) {
    return fmaxf(0.0f, 1.0f - fabsf(d));
}

// ============================================================================
// Kernel A: vproj[b,i,p,q] = sum_hw wy[h,p]*wx[w,q]*v[b,i,h,w]
// grid = B*Cin blocks (one image each), 256 threads (8 warps x 16 rows each)
// ============================================================================
__global__ __launch_bounds__(256) void kA_vproj(const float* __restrict__ v) {
    const int tid  = threadIdx.x;
    const int wid  = tid >> 5;
    const int lane = tid & 31;
    const float* vb = v + (size_t)blockIdx.x * HW;

    // per-thread wx hat weights for its 4 columns (lane*4 .. lane*4+3)
    float wxr[4][4];
#pragma unroll
    for (int c = 0; c < 4; c++) {
        float tx = ((lane << 2) + c + 0.5f) * K3;
#pragma unroll
        for (int q = 0; q < 4; q++) wxr[c][q] = hatf(tx - (float)q);
    }

    float acc[16];
#pragma unroll
    for (int t = 0; t < 16; t++) acc[t] = 0.0f;

#pragma unroll 4
    for (int rr = 0; rr < 16; rr++) {
        const int r = (wid << 4) + rr;
        float4 vv = *reinterpret_cast<const float4*>(vb + r * WW + (lane << 2));
        float s[4] = {0.f, 0.f, 0.f, 0.f};
        const float vals[4] = {vv.x, vv.y, vv.z, vv.w};
#pragma unroll
        for (int c = 0; c < 4; c++) {
#pragma unroll
            for (int q = 0; q < 4; q++) s[q] += vals[c] * wxr[c][q];
        }
        float ty = (r + 0.5f) * K3;
#pragma unroll
        for (int p = 0; p < 4; p++) {
            float hp = hatf(ty - (float)p);
#pragma unroll
            for (int q = 0; q < 4; q++) acc[p * 4 + q] += hp * s[q];
        }
    }

    // warp reduce all 16
#pragma unroll
    for (int t = 0; t < 16; t++) {
#pragma unroll
        for (int off = 16; off > 0; off >>= 1)
            acc[t] += __shfl_xor_sync(0xFFFFFFFFu, acc[t], off);
    }
    __shared__ float red[8][16];
    if (lane == 0) {
#pragma unroll
        for (int t = 0; t < 16; t++) red[wid][t] = acc[t];
    }
    __syncthreads();
    if (tid < 16) {
        float s = 0.f;
#pragma unroll
        for (int w = 0; w < 8; w++) s += red[w][tid];
        g_vproj[blockIdx.x * 16 + tid] = s;
    }
}

// ============================================================================
// Kernel B: vr[b,r] = sum k1*vproj/HW ; m[b,o,pq] = sum_r k2*vr
// grid = 8 (one per batch), 256 threads
// ============================================================================
__global__ __launch_bounds__(256) void kB_mix(const float* __restrict__ k1,
                                              const float* __restrict__ k2) {
    const int b = blockIdx.x, tid = threadIdx.x;
    __shared__ float vp[CIN * 16];
    __shared__ float part[RNK][8];
    __shared__ float vr[RNK];

    for (int i = tid; i < CIN * 16; i += 256) vp[i] = g_vproj[b * CIN * 16 + i];
    __syncthreads();

    {   // thread (r = tid/8, chunk = tid%8): 16 i's x 16 pq = 256 contiguous
        const int r = tid >> 3, ch = tid & 7;
        const float* k1p = k1 + r * (CIN * 16) + ch * 256;
        const float* vpp = vp + ch * 256;
        float p = 0.f;
#pragma unroll 8
        for (int j = 0; j < 256; j++) p += k1p[j] * vpp[j];
        part[r][ch] = p;
    }
    __syncthreads();
    if (tid < RNK) {
        float s = 0.f;
#pragma unroll
        for (int j = 0; j < 8; j++) s += part[tid][j];
        vr[tid] = s * (1.0f / (float)HW);
    }
    __syncthreads();

    for (int idx = tid; idx < COUT * 16; idx += 256) {
        float s = 0.f;
#pragma unroll
        for (int r = 0; r < RNK; r++) s += k2[r * (COUT * 16) + idx] * vr[r];
        g_m[b * COUT * 16 + idx] = s;
    }
}

// ============================================================================
// Kernel C: out[b,o,h,w] = conv_w@v (bf16 hi/lo split tensor-core GEMM)
//                        + interp(m) + conv_b + bias
// grid = (h=128, b=8), 256 threads (8 warps: 4 o-tiles x 2 w-tiles)
// ============================================================================

#define LDSM4(r0, r1, r2, r3, addr)                                        \
    asm volatile("ldmatrix.sync.aligned.m8n8.x4.shared.b16 {%0,%1,%2,%3}, [%4];" \
                 : "=r"(r0), "=r"(r1), "=r"(r2), "=r"(r3) : "r"(addr))

#define LDSM2T(r0, r1, addr)                                               \
    asm volatile("ldmatrix.sync.aligned.m8n8.x2.trans.shared.b16 {%0,%1}, [%2];" \
                 : "=r"(r0), "=r"(r1) : "r"(addr))

#define MMA16816(d, a0, a1, a2, a3, b0, b1)                                \
    asm volatile("mma.sync.aligned.m16n8k16.row.col.f32.bf16.bf16.f32 "    \
                 "{%0,%1,%2,%3}, {%4,%5,%6,%7}, {%8,%9}, {%0,%1,%2,%3};"   \
                 : "+f"(d[0]), "+f"(d[1]), "+f"(d[2]), "+f"(d[3])          \
                 : "r"(a0), "r"(a1), "r"(a2), "r"(a3), "r"(b0), "r"(b1))

__device__ __forceinline__ void split_bf16(float x, __nv_bfloat16& h, __nv_bfloat16& l) {
    h = __float2bfloat16(x);
    l = __float2bfloat16(x - __bfloat162float(h));
}

#define APAD 40   // 32 + 8 pad (bank-conflict-free ldmatrix)
#define BPAD 136  // 128 + 8 pad

__global__ __launch_bounds__(256) void kC_main(const float* __restrict__ v,
                                               const float* __restrict__ conv_w,
                                               const float* __restrict__ conv_b,
                                               const float* __restrict__ bias,
                                               float* __restrict__ out) {
    __shared__ __align__(16) __nv_bfloat16 sAhi[128][APAD];
    __shared__ __align__(16) __nv_bfloat16 sAlo[128][APAD];
    __shared__ __align__(16) __nv_bfloat16 sBhi[32][BPAD];
    __shared__ __align__(16) __nv_bfloat16 sBlo[32][BPAD];
    __shared__ __align__(16) float sM2[128][4];
    __shared__ float sCB[128];

    const int h = blockIdx.x, b = blockIdx.y;
    const int tid = threadIdx.x, wid = tid >> 5, lane = tid & 31;
    const int o_base = (wid & 3) * 32;
    const int w_base = (wid >> 2) * 64;

    // --- prologue: M2[o][q] = sum_p wy[h,p]*m[b,o,p*4+q];  CB[o] = conv_b+bias
    {
        const float ty = (h + 0.5f) * K3;
        const float wy0 = hatf(ty - 0.f), wy1 = hatf(ty - 1.f);
        const float wy2 = hatf(ty - 2.f), wy3 = hatf(ty - 3.f);
        for (int idx = tid; idx < 512; idx += 256) {
            const int o = idx >> 2, q = idx & 3;
            const float* mp = g_m + b * (COUT * 16) + o * 16 + q;
            sM2[o][q] = wy0 * mp[0] + wy1 * mp[4] + wy2 * mp[8] + wy3 * mp[12];
        }
        if (tid < 128) sCB[tid] = conv_b[tid] + bias[tid];
    }

    float acc[2][8][4];
#pragma unroll
    for (int mi = 0; mi < 2; mi++)
#pragma unroll
        for (int ni = 0; ni < 8; ni++)
#pragma unroll
            for (int c = 0; c < 4; c++) acc[mi][ni][c] = 0.0f;

    for (int kc = 0; kc < 4; kc++) {
        // load A chunk: conv_w[o][kc*32 .. +32)  (128x32 fp32 -> hi/lo bf16)
#pragma unroll
        for (int j = 0; j < 4; j++) {
            const int f4 = j * 256 + tid;
            const int o = f4 >> 3, kq = f4 & 7;          // 8 float4 per o-row
            float4 wv = *reinterpret_cast<const float4*>(conv_w + o * CIN + kc * 32 + kq * 4);
            const float vals[4] = {wv.x, wv.y, wv.z, wv.w};
#pragma unroll
            for (int c = 0; c < 4; c++) {
                __nv_bfloat16 hi, lo;
                split_bf16(vals[c], hi, lo);
                sAhi[o][kq * 4 + c] = hi;
                sAlo[o][kq * 4 + c] = lo;
            }
        }
        // load B chunk: v[b][kc*32+i][h][0..128) (32x128 fp32 -> hi/lo bf16)
#pragma unroll
        for (int j = 0; j < 4; j++) {
            const int f4 = j * 256 + tid;
            const int i = f4 >> 5, c4 = f4 & 31;         // 32 float4 per i-row
            const size_t gidx = (((size_t)b * CIN + kc * 32 + i) * HH + h) * WW + c4 * 4;
            float4 vv = *reinterpret_cast<const float4*>(v + gidx);
            const float vals[4] = {vv.x, vv.y, vv.z, vv.w};
#pragma unroll
            for (int c = 0; c < 4; c++) {
                __nv_bfloat16 hi, lo;
                split_bf16(vals[c], hi, lo);
                sBhi[i][c4 * 4 + c] = hi;
                sBlo[i][c4 * 4 + c] = lo;
            }
        }
        __syncthreads();

#pragma unroll
        for (int ks = 0; ks < 2; ks++) {
            const int k = ks * 16;
            uint32_t ahi[2][4], alo[2][4];
#pragma unroll
            for (int mi = 0; mi < 2; mi++) {
                const int row = o_base + mi * 16 + (lane & 15);
                const int koff = k + ((lane >> 4) << 3);
                uint32_t ah = (uint32_t)__cvta_generic_to_shared(&sAhi[row][koff]);
                uint32_t al = (uint32_t)__cvta_generic_to_shared(&sAlo[row][koff]);
                LDSM4(ahi[mi][0], ahi[mi][1], ahi[mi][2], ahi[mi][3], ah);
                LDSM4(alo[mi][0], alo[mi][1], alo[mi][2], alo[mi][3], al);
            }
#pragma unroll
            for (int ni = 0; ni < 8; ni++) {
                const int kr = k + (lane & 15);
                const int n = w_base + ni * 8;
                uint32_t bh0, bh1, bl0, bl1;
                uint32_t bha = (uint32_t)__cvta_generic_to_shared(&sBhi[kr][n]);
                uint32_t bla = (uint32_t)__cvta_generic_to_shared(&sBlo[kr][n]);
                LDSM2T(bh0, bh1, bha);
                LDSM2T(bl0, bl1, bla);
#pragma unroll
                for (int mi = 0; mi < 2; mi++) {
                    MMA16816(acc[mi][ni], ahi[mi][0], ahi[mi][1], ahi[mi][2], ahi[mi][3], bh0, bh1);
                    MMA16816(acc[mi][ni], ahi[mi][0], ahi[mi][1], ahi[mi][2], ahi[mi][3], bl0, bl1);
                    MMA16816(acc[mi][ni], alo[mi][0], alo[mi][1], alo[mi][2], alo[mi][3], bh0, bh1);
                }
            }
        }
        __syncthreads();
    }

    // --- epilogue: add interp term + biases, store
    const int g = lane >> 2, cq = lane & 3;
#pragma unroll
    for (int ni = 0; ni < 8; ni++) {
        const int w0 = w_base + ni * 8 + cq * 2;
        const float tx0 = (w0 + 0.5f) * K3, tx1 = tx0 + K3;
        float wxa[4], wxb[4];
#pragma unroll
        for (int q = 0; q < 4; q++) {
            wxa[q] = hatf(tx0 - (float)q);
            wxb[q] = hatf(tx1 - (float)q);
        }
#pragma unroll
        for (int mi = 0; mi < 2; mi++) {
#pragma unroll
            for (int rr = 0; rr < 2; rr++) {
                const int o = o_base + mi * 16 + g + rr * 8;
                float4 m2 = *reinterpret_cast<float4*>(&sM2[o][0]);
                const float base = sCB[o];
                float t0 = base + wxa[0] * m2.x + wxa[1] * m2.y + wxa[2] * m2.z + wxa[3] * m2.w;
                float t1 = base + wxb[0] * m2.x + wxb[1] * m2.y + wxb[2] * m2.z + wxb[3] * m2.w;
                float2 res;
                res.x = acc[mi][ni][rr * 2 + 0] + t0;
                res.y = acc[mi][ni][rr * 2 + 1] + t1;
                *reinterpret_cast<float2*>(out + (((size_t)b * COUT + o) * HH + h) * WW + w0) = res;
            }
        }
    }
}

// ============================================================================
extern "C" void kernel_launch(void* const* d_in, const int* in_sizes, int n_in,
                              void* d_out, int out_size) {
    const float* v      = (const float*)d_in[0];
    const float* k1     = (const float*)d_in[1];
    const float* k2     = (const float*)d_in[2];
    const float* conv_w = (const float*)d_in[3];
    const float* conv_b = (const float*)d_in[4];
    const float* bias   = (const float*)d_in[5];
    float* out = (float*)d_out;

    kA_vproj<<<BB * CIN, 256>>>(v);
    kB_mix<<<BB, 256>>>(k1, k2);
    kC_main<<<dim3(HH, BB), 256>>>(v, conv_w, conv_b, bias, out);
}

// round 2
// speedup vs baseline: 1.0168x; 1.0168x over previous
#include <cuda_runtime.h>
#include <cuda_bf16.h>
#include <cstdint>

// Problem constants
#define BB   8
#define CIN  128
#define COUT 128
#define HH   128
#define WW   128
#define RNK  32
#define HW   (HH*WW)
#define K3   (3.0f/128.0f)

// Scratch (no allocation allowed)
__device__ float g_vproj[BB*CIN*16];   // (b, i, p*4+q)
__device__ float g_m[BB*COUT*16];      // (b, o, p*4+q)
// conv_w pre-split into MMA A-fragment layout: [prec][o_tile(8)][kstep(8)][lane(32)] = 4 regs
__device__ uint4 g_Wfrag[2][8][8][32];

__device__ __forceinline__ float hatf(float d) {
    return fmaxf(0.0f, 1.0f - fabsf(d));
}

// split x,y into bf16 hi/lo packed pairs (low half = x)
__device__ __forceinline__ void split_pack(float x, float y, uint32_t& hi, uint32_t& lo) {
    __nv_bfloat16 hx = __float2bfloat16(x);
    __nv_bfloat16 hy = __float2bfloat16(y);
    float rx = x - __bfloat162float(hx);
    float ry = y - __bfloat162float(hy);
    __nv_bfloat162 H; H.x = hx; H.y = hy;
    __nv_bfloat162 L; L.x = __float2bfloat16(rx); L.y = __float2bfloat16(ry);
    hi = *reinterpret_cast<uint32_t*>(&H);
    lo = *reinterpret_cast<uint32_t*>(&L);
}

// ============================================================================
// Kernel W: split conv_w into A-fragment layout (runs once per launch, ~2us)
// ============================================================================
__global__ __launch_bounds__(256) void kW_split(const float* __restrict__ cw) {
    const int idx = blockIdx.x * 256 + threadIdx.x;   // 0..2047
    if (idx >= 2048) return;
    const int ot = idx >> 8, ks = (idx >> 5) & 7, lane = idx & 31;
    const int r0 = ot * 16 + (lane >> 2), r1 = r0 + 8;
    const int kb = ks * 16 + (lane & 3) * 2;

    uint32_t hi[4], lo[4];
    split_pack(cw[r0 * CIN + kb],     cw[r0 * CIN + kb + 1], hi[0], lo[0]);
    split_pack(cw[r1 * CIN + kb],     cw[r1 * CIN + kb + 1], hi[1], lo[1]);
    split_pack(cw[r0 * CIN + kb + 8], cw[r0 * CIN + kb + 9], hi[2], lo[2]);
    split_pack(cw[r1 * CIN + kb + 8], cw[r1 * CIN + kb + 9], hi[3], lo[3]);

    g_Wfrag[0][ot][ks][lane] = make_uint4(hi[0], hi[1], hi[2], hi[3]);
    g_Wfrag[1][ot][ks][lane] = make_uint4(lo[0], lo[1], lo[2], lo[3]);
}

// ============================================================================
// Kernel A: vproj[b,i,p,q] = sum_hw wy[h,p]*wx[w,q]*v[b,i,h,w]
// ============================================================================
__global__ __launch_bounds__(256) void kA_vproj(const float* __restrict__ v) {
    const int tid  = threadIdx.x;
    const int wid  = tid >> 5;
    const int lane = tid & 31;
    const float* vb = v + (size_t)blockIdx.x * HW;

    float wxr[4][4];
#pragma unroll
    for (int c = 0; c < 4; c++) {
        float tx = ((lane << 2) + c + 0.5f) * K3;
#pragma unroll
        for (int q = 0; q < 4; q++) wxr[c][q] = hatf(tx - (float)q);
    }

    float acc[16];
#pragma unroll
    for (int t = 0; t < 16; t++) acc[t] = 0.0f;

#pragma unroll 4
    for (int rr = 0; rr < 16; rr++) {
        const int r = (wid << 4) + rr;
        float4 vv = *reinterpret_cast<const float4*>(vb + r * WW + (lane << 2));
        float s[4] = {0.f, 0.f, 0.f, 0.f};
        const float vals[4] = {vv.x, vv.y, vv.z, vv.w};
#pragma unroll
        for (int c = 0; c < 4; c++) {
#pragma unroll
            for (int q = 0; q < 4; q++) s[q] += vals[c] * wxr[c][q];
        }
        float ty = (r + 0.5f) * K3;
#pragma unroll
        for (int p = 0; p < 4; p++) {
            float hp = hatf(ty - (float)p);
#pragma unroll
            for (int q = 0; q < 4; q++) acc[p * 4 + q] += hp * s[q];
        }
    }

#pragma unroll
    for (int t = 0; t < 16; t++) {
#pragma unroll
        for (int off = 16; off > 0; off >>= 1)
            acc[t] += __shfl_xor_sync(0xFFFFFFFFu, acc[t], off);
    }
    __shared__ float red[8][16];
    if (lane == 0) {
#pragma unroll
        for (int t = 0; t < 16; t++) red[wid][t] = acc[t];
    }
    __syncthreads();
    if (tid < 16) {
        float s = 0.f;
#pragma unroll
        for (int w = 0; w < 8; w++) s += red[w][tid];
        g_vproj[blockIdx.x * 16 + tid] = s;
    }
}

// ============================================================================
// Kernel B: vr[b,r] = sum k1*vproj/HW ; m[b,o,pq] = sum_r k2*vr
// ============================================================================
__global__ __launch_bounds__(256) void kB_mix(const float* __restrict__ k1,
                                              const float* __restrict__ k2) {
    const int b = blockIdx.x, tid = threadIdx.x;
    __shared__ float vp[CIN * 16];
    __shared__ float part[RNK][8];
    __shared__ float vr[RNK];

    for (int i = tid; i < CIN * 16; i += 256) vp[i] = g_vproj[b * CIN * 16 + i];
    __syncthreads();

    {
        const int r = tid >> 3, ch = tid & 7;
        const float* k1p = k1 + r * (CIN * 16) + ch * 256;
        const float* vpp = vp + ch * 256;
        float p = 0.f;
#pragma unroll 8
        for (int j = 0; j < 256; j++) p += k1p[j] * vpp[j];
        part[r][ch] = p;
    }
    __syncthreads();
    if (tid < RNK) {
        float s = 0.f;
#pragma unroll
        for (int j = 0; j < 8; j++) s += part[tid][j];
        vr[tid] = s * (1.0f / (float)HW);
    }
    __syncthreads();

    for (int idx = tid; idx < COUT * 16; idx += 256) {
        float s = 0.f;
#pragma unroll
        for (int r = 0; r < RNK; r++) s += k2[r * (COUT * 16) + idx] * vr[r];
        g_m[b * COUT * 16 + idx] = s;
    }
}

// ============================================================================
// Kernel C: out[b,o,h,w] = conv_w@v (bf16 hi/lo split) + interp(m) + biases
// grid = (h=128, b=8), 256 threads (8 warps: 4 o-tiles x 2 w-tiles of 32x64)
// cp.async pipeline: stage fp32 chunk kc+1 while MMAs run on chunk kc.
// A fragments loaded directly from g_Wfrag with LDG.128 (L1-resident).
// ============================================================================

#define LDSM4T(r0, r1, r2, r3, addr)                                            \
    asm volatile("ldmatrix.sync.aligned.m8n8.x4.trans.shared.b16 {%0,%1,%2,%3}, [%4];" \
                 : "=r"(r0), "=r"(r1), "=r"(r2), "=r"(r3) : "r"(addr))

#define MMA16816(d, a0, a1, a2, a3, b0, b1)                                \
    asm volatile("mma.sync.aligned.m16n8k16.row.col.f32.bf16.bf16.f32 "    \
                 "{%0,%1,%2,%3}, {%4,%5,%6,%7}, {%8,%9}, {%0,%1,%2,%3};"   \
                 : "+f"(d[0]), "+f"(d[1]), "+f"(d[2]), "+f"(d[3])          \
                 : "r"(a0), "r"(a1), "r"(a2), "r"(a3), "r"(b0), "r"(b1))

#define CP_ASYNC16(dst, src) \
    asm volatile("cp.async.cg.shared.global [%0], [%1], 16;" :: "r"(dst), "l"(src))
#define CP_COMMIT() asm volatile("cp.async.commit_group;")
#define CP_WAIT0()  asm volatile("cp.async.wait_group 0;")

#define BPAD 136  // 128 + 8 pad

__global__ __launch_bounds__(256, 2) void kC_main(const float* __restrict__ v,
                                                  const float* __restrict__ conv_b,
                                                  const float* __restrict__ bias,
                                                  float* __restrict__ out) {
    __shared__ __align__(16) float sStage[32 * 128];          // fp32 v chunk
    __shared__ __align__(16) __nv_bfloat16 sBhi[32][BPAD];
    __shared__ __align__(16) __nv_bfloat16 sBlo[32][BPAD];
    __shared__ __align__(16) float sM2[128][4];
    __shared__ float sCB[128];

    const int h = blockIdx.x, b = blockIdx.y;
    const int tid = threadIdx.x, wid = tid >> 5, lane = tid & 31;
    const int o_base = (wid & 3) * 32;
    const int w_base = (wid >> 2) * 64;
    const int ot0 = (wid & 3) * 2;

    // issue cp.async for chunk 0 immediately
    {
#pragma unroll
        for (int j = 0; j < 4; j++) {
            const int f = j * 256 + tid;
            const int i = f >> 5, sg = f & 31;
            const float* src = v + (((size_t)b * CIN + i) * HH + h) * WW + sg * 4;
            uint32_t dst = (uint32_t)__cvta_generic_to_shared(&sStage[i * 128 + sg * 4]);
            CP_ASYNC16(dst, src);
        }
        CP_COMMIT();
    }

    // prologue: M2[o][q] = sum_p wy[h,p]*m[b,o,p*4+q];  CB[o] = conv_b+bias
    {
        const float ty = (h + 0.5f) * K3;
        const float wy0 = hatf(ty - 0.f), wy1 = hatf(ty - 1.f);
        const float wy2 = hatf(ty - 2.f), wy3 = hatf(ty - 3.f);
        for (int idx = tid; idx < 512; idx += 256) {
            const int o = idx >> 2, q = idx & 3;
            const float* mp = g_m + b * (COUT * 16) + o * 16 + q;
            sM2[o][q] = wy0 * mp[0] + wy1 * mp[4] + wy2 * mp[8] + wy3 * mp[12];
        }
        if (tid < 128) sCB[tid] = conv_b[tid] + bias[tid];
    }

    float acc[2][8][4];
#pragma unroll
    for (int mi = 0; mi < 2; mi++)
#pragma unroll
        for (int ni = 0; ni < 8; ni++)
#pragma unroll
            for (int c = 0; c < 4; c++) acc[mi][ni][c] = 0.0f;

    for (int kc = 0; kc < 4; kc++) {
        CP_WAIT0();
        __syncthreads();   // stage ready; previous compute done (sB reusable)

        // convert fp32 stage -> bf16 hi/lo smem (packed bf16x2 stores)
#pragma unroll
        for (int j = 0; j < 4; j++) {
            const int f4 = j * 256 + tid;
            const int i = f4 >> 5, c4 = f4 & 31;
            float4 vv = *reinterpret_cast<const float4*>(&sStage[i * 128 + c4 * 4]);
            uint32_t h0, l0, h1, l1;
            split_pack(vv.x, vv.y, h0, l0);
            split_pack(vv.z, vv.w, h1, l1);
            uint32_t* ph = reinterpret_cast<uint32_t*>(&sBhi[i][c4 * 4]);
            uint32_t* pl = reinterpret_cast<uint32_t*>(&sBlo[i][c4 * 4]);
            ph[0] = h0; ph[1] = h1;
            pl[0] = l0; pl[1] = l1;
        }
        __syncthreads();   // stage fully consumed, sB ready

        // prefetch next chunk into stage (overlaps with MMA below)
        if (kc < 3) {
#pragma unroll
            for (int j = 0; j < 4; j++) {
                const int f = j * 256 + tid;
                const int i = f >> 5, sg = f & 31;
                const float* src = v + (((size_t)b * CIN + (kc + 1) * 32 + i) * HH + h) * WW + sg * 4;
                uint32_t dst = (uint32_t)__cvta_generic_to_shared(&sStage[i * 128 + sg * 4]);
                CP_ASYNC16(dst, src);
            }
            CP_COMMIT();
        }

        // compute: 2 k-steps of 16
#pragma unroll
        for (int ks = 0; ks < 2; ks++) {
            const int gks = kc * 2 + ks;
            uint4 AH[2], AL[2];
#pragma unroll
            for (int mi = 0; mi < 2; mi++) {
                AH[mi] = g_Wfrag[0][ot0 + mi][gks][lane];
                AL[mi] = g_Wfrag[1][ot0 + mi][gks][lane];
            }
            const int kr = ks * 16 + (lane & 15);
            const int csub = ((lane >> 4) << 3);
#pragma unroll
            for (int ng = 0; ng < 4; ng++) {
                const int col = w_base + ng * 16 + csub;
                uint32_t bh0, bh1, bh2, bh3, bl0, bl1, bl2, bl3;
                uint32_t ah = (uint32_t)__cvta_generic_to_shared(&sBhi[kr][col]);
                uint32_t al = (uint32_t)__cvta_generic_to_shared(&sBlo[kr][col]);
                LDSM4T(bh0, bh1, bh2, bh3, ah);
                LDSM4T(bl0, bl1, bl2, bl3, al);
#pragma unroll
                for (int mi = 0; mi < 2; mi++) {
                    float* d0 = acc[mi][ng * 2 + 0];
                    float* d1 = acc[mi][ng * 2 + 1];
                    MMA16816(d0, AH[mi].x, AH[mi].y, AH[mi].z, AH[mi].w, bh0, bh1);
                    MMA16816(d0, AL[mi].x, AL[mi].y, AL[mi].z, AL[mi].w, bh0, bh1);
                    MMA16816(d0, AH[mi].x, AH[mi].y, AH[mi].z, AH[mi].w, bl0, bl1);
                    MMA16816(d1, AH[mi].x, AH[mi].y, AH[mi].z, AH[mi].w, bh2, bh3);
                    MMA16816(d1, AL[mi].x, AL[mi].y, AL[mi].z, AL[mi].w, bh2, bh3);
                    MMA16816(d1, AH[mi].x, AH[mi].y, AH[mi].z, AH[mi].w, bl2, bl3);
                }
            }
        }
        __syncthreads();
    }

    // epilogue: add interp term + biases, store
    const int g = lane >> 2, cq = lane & 3;
#pragma unroll
    for (int ni = 0; ni < 8; ni++) {
        const int w0 = w_base + ni * 8 + cq * 2;
        const float tx0 = (w0 + 0.5f) * K3, tx1 = tx0 + K3;
        float wxa[4], wxb[4];
#pragma unroll
        for (int q = 0; q < 4; q++) {
            wxa[q] = hatf(tx0 - (float)q);
            wxb[q] = hatf(tx1 - (float)q);
        }
#pragma unroll
        for (int mi = 0; mi < 2; mi++) {
#pragma unroll
            for (int rr = 0; rr < 2; rr++) {
                const int o = o_base + mi * 16 + g + rr * 8;
                float4 m2 = *reinterpret_cast<float4*>(&sM2[o][0]);
                const float base = sCB[o];
                float t0 = base + wxa[0] * m2.x + wxa[1] * m2.y + wxa[2] * m2.z + wxa[3] * m2.w;
                float t1 = base + wxb[0] * m2.x + wxb[1] * m2.y + wxb[2] * m2.z + wxb[3] * m2.w;
                float2 res;
                res.x = acc[mi][ni][rr * 2 + 0] + t0;
                res.y = acc[mi][ni][rr * 2 + 1] + t1;
                *reinterpret_cast<float2*>(out + (((size_t)b * COUT + o) * HH + h) * WW + w0) = res;
            }
        }
    }
}

// ============================================================================
extern "C" void kernel_launch(void* const* d_in, const int* in_sizes, int n_in,
                              void* d_out, int out_size) {
    const float* v      = (const float*)d_in[0];
    const float* k1     = (const float*)d_in[1];
    const float* k2     = (const float*)d_in[2];
    const float* conv_w = (const float*)d_in[3];
    const float* conv_b = (const float*)d_in[4];
    const float* bias   = (const float*)d_in[5];
    float* out = (float*)d_out;

    kW_split<<<8, 256>>>(conv_w);
    kA_vproj<<<BB * CIN, 256>>>(v);
    kB_mix<<<BB, 256>>>(k1, k2);
    kC_main<<<dim3(HH, BB), 256>>>(v, conv_b, bias, out);
}

// round 3
// speedup vs baseline: 1.8499x; 1.8193x over previous
#include <cuda_runtime.h>
#include <cuda_bf16.h>
#include <cstdint>

// Problem constants
#define BB   8
#define CIN  128
#define COUT 128
#define HH   128
#define WW   128
#define RNK  32
#define HW   (HH*WW)
#define K3   (3.0f/128.0f)

// Scratch (no allocation allowed)
__device__ float g_vproj[BB*CIN*16];   // (b, i, p*4+q)
__device__ float g_vr[BB*RNK];         // (b, r)
__device__ float g_m[BB*COUT*16];      // (b, o, p*4+q)
// conv_w pre-split into MMA A-fragment layout: [prec][o_tile(8)][kstep(8)][lane(32)]
__device__ uint4 g_Wfrag[2][8][8][32];

__device__ __forceinline__ float hatf(float d) {
    return fmaxf(0.0f, 1.0f - fabsf(d));
}

// split x,y into bf16 hi/lo packed pairs (low half = x)
__device__ __forceinline__ void split_pack(float x, float y, uint32_t& hi, uint32_t& lo) {
    __nv_bfloat16 hx = __float2bfloat16(x);
    __nv_bfloat16 hy = __float2bfloat16(y);
    float rx = x - __bfloat162float(hx);
    float ry = y - __bfloat162float(hy);
    __nv_bfloat162 H; H.x = hx; H.y = hy;
    __nv_bfloat162 L; L.x = __float2bfloat16(rx); L.y = __float2bfloat16(ry);
    hi = *reinterpret_cast<uint32_t*>(&H);
    lo = *reinterpret_cast<uint32_t*>(&L);
}

// ============================================================================
// Kernel W: split conv_w into A-fragment layout (once, ~2us)
// ============================================================================
__global__ __launch_bounds__(256) void kW_split(const float* __restrict__ cw) {
    const int idx = blockIdx.x * 256 + threadIdx.x;   // 0..2047
    if (idx >= 2048) return;
    const int ot = idx >> 8, ks = (idx >> 5) & 7, lane = idx & 31;
    const int r0 = ot * 16 + (lane >> 2), r1 = r0 + 8;
    const int kb = ks * 16 + (lane & 3) * 2;

    uint32_t hi[4], lo[4];
    split_pack(cw[r0 * CIN + kb],     cw[r0 * CIN + kb + 1], hi[0], lo[0]);
    split_pack(cw[r1 * CIN + kb],     cw[r1 * CIN + kb + 1], hi[1], lo[1]);
    split_pack(cw[r0 * CIN + kb + 8], cw[r0 * CIN + kb + 9], hi[2], lo[2]);
    split_pack(cw[r1 * CIN + kb + 8], cw[r1 * CIN + kb + 9], hi[3], lo[3]);

    g_Wfrag[0][ot][ks][lane] = make_uint4(hi[0], hi[1], hi[2], hi[3]);
    g_Wfrag[1][ot][ks][lane] = make_uint4(lo[0], lo[1], lo[2], lo[3]);
}

// ============================================================================
// Kernel A: vproj[b,i,p,q] = sum_hw wy[h,p]*wx[w,q]*v[b,i,h,w]
// grid = B*Cin, 256 threads
// ============================================================================
__global__ __launch_bounds__(256) void kA_vproj(const float* __restrict__ v) {
    const int tid  = threadIdx.x;
    const int wid  = tid >> 5;
    const int lane = tid & 31;
    const float* vb = v + (size_t)blockIdx.x * HW;

    float wxr[4][4];
#pragma unroll
    for (int c = 0; c < 4; c++) {
        float tx = ((lane << 2) + c + 0.5f) * K3;
#pragma unroll
        for (int q = 0; q < 4; q++) wxr[c][q] = hatf(tx - (float)q);
    }

    float acc[16];
#pragma unroll
    for (int t = 0; t < 16; t++) acc[t] = 0.0f;

    // issue all 16 row loads up front for max MLP
    float4 rows[16];
#pragma unroll
    for (int rr = 0; rr < 16; rr++) {
        const int r = (wid << 4) + rr;
        rows[rr] = *reinterpret_cast<const float4*>(vb + r * WW + (lane << 2));
    }

#pragma unroll
    for (int rr = 0; rr < 16; rr++) {
        const int r = (wid << 4) + rr;
        float s[4] = {0.f, 0.f, 0.f, 0.f};
        const float vals[4] = {rows[rr].x, rows[rr].y, rows[rr].z, rows[rr].w};
#pragma unroll
        for (int c = 0; c < 4; c++) {
#pragma unroll
            for (int q = 0; q < 4; q++) s[q] += vals[c] * wxr[c][q];
        }
        float ty = (r + 0.5f) * K3;
#pragma unroll
        for (int p = 0; p < 4; p++) {
            float hp = hatf(ty - (float)p);
#pragma unroll
            for (int q = 0; q < 4; q++) acc[p * 4 + q] += hp * s[q];
        }
    }

#pragma unroll
    for (int t = 0; t < 16; t++) {
#pragma unroll
        for (int off = 16; off > 0; off >>= 1)
            acc[t] += __shfl_xor_sync(0xFFFFFFFFu, acc[t], off);
    }
    __shared__ float red[8][16];
    if (lane == 0) {
#pragma unroll
        for (int t = 0; t < 16; t++) red[wid][t] = acc[t];
    }
    __syncthreads();
    if (tid < 16) {
        float s = 0.f;
#pragma unroll
        for (int w = 0; w < 8; w++) s += red[w][tid];
        g_vproj[blockIdx.x * 16 + tid] = s;
    }
}

// ============================================================================
// Kernel B1: vr[b,r] = dot(k1[r,:,:], vproj[b,:,:]) / HW
// grid = (r=32, b=8), 256 threads; each block reads 8KB of k1 + 8KB vproj
// ============================================================================
__global__ __launch_bounds__(256) void kB1_vr(const float* __restrict__ k1) {
    const int r = blockIdx.x, b = blockIdx.y;
    const int tid = threadIdx.x, wid = tid >> 5, lane = tid & 31;
    const float* k1p = k1 + (size_t)r * (CIN * 16);
    const float* vpp = g_vproj + (size_t)b * (CIN * 16);

    // 2048 elements / 256 threads = 8 each (2 float4)
    float s = 0.f;
#pragma unroll
    for (int j = 0; j < 2; j++) {
        const int e = (j * 256 + tid) * 4;
        float4 a = *reinterpret_cast<const float4*>(k1p + e);
        float4 c = *reinterpret_cast<const float4*>(vpp + e);
        s += a.x * c.x + a.y * c.y + a.z * c.z + a.w * c.w;
    }
#pragma unroll
    for (int off = 16; off > 0; off >>= 1)
        s += __shfl_xor_sync(0xFFFFFFFFu, s, off);
    __shared__ float red[8];
    if (lane == 0) red[wid] = s;
    __syncthreads();
    if (tid == 0) {
        float t = 0.f;
#pragma unroll
        for (int w = 0; w < 8; w++) t += red[w];
        g_vr[b * RNK + r] = t * (1.0f / (float)HW);
    }
}

// ============================================================================
// Kernel B2: m[b,o,pq] = sum_r k2[r,o,pq] * vr[b,r]
// grid = (chunk=8, b=8), 256 threads; coalesced k2 reads
// ============================================================================
__global__ __launch_bounds__(256) void kB2_m(const float* __restrict__ k2) {
    const int ch = blockIdx.x, b = blockIdx.y, tid = threadIdx.x;
    __shared__ float vr[RNK];
    if (tid < RNK) vr[tid] = g_vr[b * RNK + tid];
    __syncthreads();

    const int idx = ch * 256 + tid;   // 0..2047 over (o,pq)
    float s = 0.f;
#pragma unroll
    for (int r = 0; r < RNK; r++)
        s += k2[(size_t)r * (COUT * 16) + idx] * vr[r];
    g_m[b * (COUT * 16) + idx] = s;
}

// ============================================================================
// Kernel C: out = conv_w@v (bf16 hi/lo split, tensor cores) + interp(m) + biases
// grid = (h=128, b=8), 256 threads (8 warps: 4 o-tiles x 2 w-tiles of 32x64)
// Double-buffered bf16 smem; register prefetch of next fp32 chunk overlaps MMA.
// ============================================================================

#define LDSM4T(r0, r1, r2, r3, addr)                                            \
    asm volatile("ldmatrix.sync.aligned.m8n8.x4.trans.shared.b16 {%0,%1,%2,%3}, [%4];" \
                 : "=r"(r0), "=r"(r1), "=r"(r2), "=r"(r3) : "r"(addr))

#define MMA16816(d, a0, a1, a2, a3, b0, b1)                                \
    asm volatile("mma.sync.aligned.m16n8k16.row.col.f32.bf16.bf16.f32 "    \
                 "{%0,%1,%2,%3}, {%4,%5,%6,%7}, {%8,%9}, {%0,%1,%2,%3};"   \
                 : "+f"(d[0]), "+f"(d[1]), "+f"(d[2]), "+f"(d[3])          \
                 : "r"(a0), "r"(a1), "r"(a2), "r"(a3), "r"(b0), "r"(b1))

#define BPAD 136  // 128 + 8 pad

__global__ __launch_bounds__(256, 2) void kC_main(const float* __restrict__ v,
                                                  const float* __restrict__ conv_b,
                                                  const float* __restrict__ bias,
                                                  float* __restrict__ out) {
    __shared__ __align__(16) __nv_bfloat16 sBhi[2][32][BPAD];
    __shared__ __align__(16) __nv_bfloat16 sBlo[2][32][BPAD];
    __shared__ __align__(16) float sM2[128][4];
    __shared__ float sCB[128];

    const int h = blockIdx.x, b = blockIdx.y;
    const int tid = threadIdx.x, wid = tid >> 5, lane = tid & 31;
    const int o_base = (wid & 3) * 32;
    const int w_base = (wid >> 2) * 64;
    const int ot0 = (wid & 3) * 2;

    // thread's fixed (i, c4) slot within a 32x128 chunk
    const int li = tid >> 3;          // 0..31  (i row)
    const int lc = tid & 7;           // 0..7   (c4 group of 16 floats)
    const float* vbase = v + (((size_t)b * CIN + li) * HH + h) * WW + lc * 16;

    // prefetch chunk 0 into registers (4 float4 per thread, 16 floats)
    float4 R[4];
#pragma unroll
    for (int j = 0; j < 4; j++) R[j] = *reinterpret_cast<const float4*>(vbase + j * 4);

    // prologue: M2[o][q] = sum_p wy[h,p]*m[b,o,p*4+q];  CB[o] = conv_b+bias
    {
        const float ty = (h + 0.5f) * K3;
        const float wy0 = hatf(ty - 0.f), wy1 = hatf(ty - 1.f);
        const float wy2 = hatf(ty - 2.f), wy3 = hatf(ty - 3.f);
        for (int idx = tid; idx < 512; idx += 256) {
            const int o = idx >> 2, q = idx & 3;
            const float* mp = g_m + b * (COUT * 16) + o * 16 + q;
            sM2[o][q] = wy0 * mp[0] + wy1 * mp[4] + wy2 * mp[8] + wy3 * mp[12];
        }
        if (tid < 128) sCB[tid] = conv_b[tid] + bias[tid];
    }

    float acc[2][8][4];
#pragma unroll
    for (int mi = 0; mi < 2; mi++)
#pragma unroll
        for (int ni = 0; ni < 8; ni++)
#pragma unroll
            for (int c = 0; c < 4; c++) acc[mi][ni][c] = 0.0f;

    for (int kc = 0; kc < 4; kc++) {
        const int buf = kc & 1;
        // convert register chunk -> bf16 hi/lo smem (STS.64, conflict-free)
#pragma unroll
        for (int j = 0; j < 4; j++) {
            uint32_t h0, l0, h1, l1;
            split_pack(R[j].x, R[j].y, h0, l0);
            split_pack(R[j].z, R[j].w, h1, l1);
            *reinterpret_cast<uint2*>(&sBhi[buf][li][lc * 16 + j * 4]) = make_uint2(h0, h1);
            *reinterpret_cast<uint2*>(&sBlo[buf][li][lc * 16 + j * 4]) = make_uint2(l0, l1);
        }
        __syncthreads();

        // prefetch next chunk into registers (overlaps MMA below)
        if (kc < 3) {
            const float* src = vbase + (size_t)(kc + 1) * 32 * HW;
#pragma unroll
            for (int j = 0; j < 4; j++) R[j] = *reinterpret_cast<const float4*>(src + j * 4);
        }

        // compute: 2 k-steps of 16
#pragma unroll
        for (int ks = 0; ks < 2; ks++) {
            const int gks = kc * 2 + ks;
            uint4 AH[2], AL[2];
#pragma unroll
            for (int mi = 0; mi < 2; mi++) {
                AH[mi] = g_Wfrag[0][ot0 + mi][gks][lane];
                AL[mi] = g_Wfrag[1][ot0 + mi][gks][lane];
            }
            const int kr = ks * 16 + (lane & 15);
            const int csub = ((lane >> 4) << 3);
#pragma unroll
            for (int ng = 0; ng < 4; ng++) {
                const int col = w_base + ng * 16 + csub;
                uint32_t bh0, bh1, bh2, bh3, bl0, bl1, bl2, bl3;
                uint32_t ah = (uint32_t)__cvta_generic_to_shared(&sBhi[buf][kr][col]);
                uint32_t al = (uint32_t)__cvta_generic_to_shared(&sBlo[buf][kr][col]);
                LDSM4T(bh0, bh1, bh2, bh3, ah);
                LDSM4T(bl0, bl1, bl2, bl3, al);
#pragma unroll
                for (int mi = 0; mi < 2; mi++) {
                    float* d0 = acc[mi][ng * 2 + 0];
                    float* d1 = acc[mi][ng * 2 + 1];
                    MMA16816(d0, AH[mi].x, AH[mi].y, AH[mi].z, AH[mi].w, bh0, bh1);
                    MMA16816(d0, AL[mi].x, AL[mi].y, AL[mi].z, AL[mi].w, bh0, bh1);
                    MMA16816(d0, AH[mi].x, AH[mi].y, AH[mi].z, AH[mi].w, bl0, bl1);
                    MMA16816(d1, AH[mi].x, AH[mi].y, AH[mi].z, AH[mi].w, bh2, bh3);
                    MMA16816(d1, AL[mi].x, AL[mi].y, AL[mi].z, AL[mi].w, bh2, bh3);
                    MMA16816(d1, AH[mi].x, AH[mi].y, AH[mi].z, AH[mi].w, bl2, bl3);
                }
            }
        }
        // no trailing barrier needed: next iter's STS targets the other buffer,
        // and the next __syncthreads orders buffer reuse two iterations apart.
    }

    // epilogue: add interp term + biases, store
    const int g = lane >> 2, cq = lane & 3;
#pragma unroll
    for (int ni = 0; ni < 8; ni++) {
        const int w0 = w_base + ni * 8 + cq * 2;
        const float tx0 = (w0 + 0.5f) * K3, tx1 = tx0 + K3;
        float wxa[4], wxb[4];
#pragma unroll
        for (int q = 0; q < 4; q++) {
            wxa[q] = hatf(tx0 - (float)q);
            wxb[q] = hatf(tx1 - (float)q);
        }
#pragma unroll
        for (int mi = 0; mi < 2; mi++) {
#pragma unroll
            for (int rr = 0; rr < 2; rr++) {
                const int o = o_base + mi * 16 + g + rr * 8;
                float4 m2 = *reinterpret_cast<float4*>(&sM2[o][0]);
                const float base = sCB[o];
                float t0 = base + wxa[0] * m2.x + wxa[1] * m2.y + wxa[2] * m2.z + wxa[3] * m2.w;
                float t1 = base + wxb[0] * m2.x + wxb[1] * m2.y + wxb[2] * m2.z + wxb[3] * m2.w;
                float2 res;
                res.x = acc[mi][ni][rr * 2 + 0] + t0;
                res.y = acc[mi][ni][rr * 2 + 1] + t1;
                *reinterpret_cast<float2*>(out + (((size_t)b * COUT + o) * HH + h) * WW + w0) = res;
            }
        }
    }
}

// ============================================================================
extern "C" void kernel_launch(void* const* d_in, const int* in_sizes, int n_in,
                              void* d_out, int out_size) {
    const float* v      = (const float*)d_in[0];
    const float* k1     = (const float*)d_in[1];
    const float* k2     = (const float*)d_in[2];
    const float* conv_w = (const float*)d_in[3];
    const float* conv_b = (const float*)d_in[4];
    const float* bias   = (const float*)d_in[5];
    float* out = (float*)d_out;

    kW_split<<<8, 256>>>(conv_w);
    kA_vproj<<<BB * CIN, 256>>>(v);
    kB1_vr<<<dim3(RNK, BB), 256>>>(k1);
    kB2_m<<<dim3(8, BB), 256>>>(k2);
    kC_main<<<dim3(HH, BB), 256>>>(v, conv_b, bias, out);
}